// round 3
// baseline (speedup 1.0000x reference)
#include <cuda_runtime.h>

#define N_NODES 100000
#define N_EDGES 1600000
#define F_IN    128
#define HID     64
#define NCLS    16

// ---------------- scratch (no allocations allowed) ----------------
__device__ int   g_is64;                        // 1 if edge_index is int64, 0 if int32
__device__ float g_dinv[N_NODES];
__device__ int   g_src[N_EDGES];
__device__ int   g_dst[N_EDGES];
__device__ float g_norm[N_EDGES];
__device__ __align__(16) float g_xw[(size_t)N_NODES * HID];   // GEMM output
__device__ __align__(16) float g_h [(size_t)N_NODES * HID];   // aggregated hidden

// ---------------- edge-index dtype detection ----------------
// int32 data read as int64 = lo + (hi<<32); hi is another node index, almost
// never 0 sixteen times in a row -> reliable discrimination.
__global__ void detect_kernel(const void* ei_raw) {
    const long long* e64 = (const long long*)ei_raw;
    int ok = 1;
    for (int i = 0; i < 16; i++) {
        long long v = e64[i];
        if (v < 0 || v >= N_NODES) ok = 0;
    }
    g_is64 = ok;
}

// ---------------- edge prep: sanitize indices into int32 ----------------
__global__ void prep_idx_kernel(const void* ei_raw) {
    int e = blockIdx.x * blockDim.x + threadIdx.x;
    if (e >= N_EDGES) return;
    int s, d;
    if (g_is64) {
        const long long* e64 = (const long long*)ei_raw;
        s = (int)e64[e];
        d = (int)e64[(size_t)N_EDGES + e];
    } else {
        const int* e32 = (const int*)ei_raw;
        s = e32[e];
        d = e32[N_EDGES + e];
    }
    // clamp: never allow a wild atomic address even if dtype guess is wrong
    if ((unsigned)s >= N_NODES) s = 0;
    if ((unsigned)d >= N_NODES) d = 0;
    g_src[e] = s;
    g_dst[e] = d;
}

// ---------------- degree / normalization ----------------
__global__ void deg_init_kernel() {
    int i = blockIdx.x * blockDim.x + threadIdx.x;
    if (i < N_NODES) g_dinv[i] = 1.0f;          // self-loop contributes 1
}

__global__ void deg_accum_kernel() {
    int e = blockIdx.x * blockDim.x + threadIdx.x;
    if (e < N_EDGES) atomicAdd(&g_dinv[g_dst[e]], 1.0f);
}

__global__ void deg_finish_kernel() {
    int i = blockIdx.x * blockDim.x + threadIdx.x;
    if (i < N_NODES) g_dinv[i] = rsqrtf(g_dinv[i]);  // deg >= 1 always
}

__global__ void norm_kernel() {
    int e = blockIdx.x * blockDim.x + threadIdx.x;
    if (e < N_EDGES) g_norm[e] = g_dinv[g_src[e]] * g_dinv[g_dst[e]];
}

// ---------------- GEMM: g_xw[node, :] = act(src[node, :]) @ W ----------------
// 8 warps/block, one node per warp per iteration, W cached in smem.
template<int K, int C, bool RELU, bool FROM_H>
__global__ void __launch_bounds__(256) gemm_kernel(const float* __restrict__ X,
                                                   const float* __restrict__ W) {
    __shared__ float Ws[K * C];
    __shared__ float xs[8][K];
    for (int i = threadIdx.x; i < K * C; i += 256) Ws[i] = W[i];
    __syncthreads();

    const int warp = threadIdx.x >> 5;
    const int lane = threadIdx.x & 31;
    constexpr int CP = (C + 31) / 32;

    for (int node = blockIdx.x * 8 + warp; node < N_NODES; node += gridDim.x * 8) {
        for (int k = lane; k < K; k += 32) {
            float v = FROM_H ? g_h[(size_t)node * K + k]
                             : X  [(size_t)node * K + k];
            if (RELU) v = fmaxf(v, 0.0f);
            xs[warp][k] = v;
        }
        __syncwarp();

        float acc[CP];
        #pragma unroll
        for (int j = 0; j < CP; j++) acc[j] = 0.0f;

        #pragma unroll
        for (int k = 0; k < K; k++) {
            float xv = xs[warp][k];
            #pragma unroll
            for (int j = 0; j < CP; j++) {
                int col = lane + 32 * j;
                if (col < C) acc[j] = fmaf(xv, Ws[k * C + col], acc[j]);
            }
        }

        #pragma unroll
        for (int j = 0; j < CP; j++) {
            int col = lane + 32 * j;
            if (col < C) g_xw[(size_t)node * C + col] = acc[j];
        }
        __syncwarp();
    }
}

// ---------------- aggregation ----------------
// dst[i,c] = b[c] + g_xw[i,c] * dinv[i]^2   (bias + self-loop term)
template<int C, bool TO_OUT>
__global__ void agg_init_kernel(const float* __restrict__ b,
                                float* __restrict__ out) {
    int idx = blockIdx.x * blockDim.x + threadIdx.x;
    if (idx >= N_NODES * C) return;
    int node = idx / C;
    int c    = idx - node * C;
    float di = g_dinv[node];
    float v  = fmaf(g_xw[idx], di * di, b[c]);
    if (TO_OUT) out[idx] = v;
    else        g_h[idx] = v;
}

// dst[d,c] += g_xw[s,c] * norm[e]   — float4 gather, 4 scalar atomics
template<int C, bool TO_OUT>
__global__ void agg_edges_kernel(float* __restrict__ out) {
    constexpr int Q = C / 4;                      // float4 chunks per edge
    int idx = blockIdx.x * blockDim.x + threadIdx.x;
    if (idx >= N_EDGES * Q) return;
    int e = idx / Q;
    int q = idx - e * Q;
    int s = g_src[e];
    int d = g_dst[e];
    float nrm = g_norm[e];
    const float4 v = *reinterpret_cast<const float4*>(g_xw + (size_t)s * C + q * 4);
    float* o = (TO_OUT ? out : g_h) + (size_t)d * C + q * 4;
    atomicAdd(o + 0, v.x * nrm);
    atomicAdd(o + 1, v.y * nrm);
    atomicAdd(o + 2, v.z * nrm);
    atomicAdd(o + 3, v.w * nrm);
}

// ---------------- launch ----------------
extern "C" void kernel_launch(void* const* d_in, const int* in_sizes, int n_in,
                              void* d_out, int out_size) {
    const float* x  = (const float*)d_in[0];
    const void*  ei = d_in[1];
    const float* W1 = (const float*)d_in[2];
    const float* b1 = (const float*)d_in[3];
    const float* W2 = (const float*)d_in[4];
    const float* b2 = (const float*)d_in[5];
    const float* W3 = (const float*)d_in[6];
    const float* b3 = (const float*)d_in[7];
    float* out = (float*)d_out;

    const int T = 256;
    const int nb_nodes = (N_NODES + T - 1) / T;
    const int nb_edges = (N_EDGES + T - 1) / T;

    // edge prep + normalization (all indices sanitized before any atomic)
    detect_kernel   <<<1, 1>>>(ei);
    prep_idx_kernel <<<nb_edges, T>>>(ei);
    deg_init_kernel  <<<nb_nodes, T>>>();
    deg_accum_kernel <<<nb_edges, T>>>();
    deg_finish_kernel<<<nb_nodes, T>>>();
    norm_kernel      <<<nb_edges, T>>>();

    const int GEMM_GRID = 592;

    // layer 1
    gemm_kernel<F_IN, HID, false, false><<<GEMM_GRID, T>>>(x, W1);
    agg_init_kernel <HID, false><<<(N_NODES * HID + T - 1) / T, T>>>(b1, nullptr);
    agg_edges_kernel<HID, false><<<(N_EDGES * (HID / 4) + T - 1) / T, T>>>(nullptr);

    // layer 2
    gemm_kernel<HID, HID, true, true><<<GEMM_GRID, T>>>(nullptr, W2);
    agg_init_kernel <HID, false><<<(N_NODES * HID + T - 1) / T, T>>>(b2, nullptr);
    agg_edges_kernel<HID, false><<<(N_EDGES * (HID / 4) + T - 1) / T, T>>>(nullptr);

    // layer 3
    gemm_kernel<HID, NCLS, true, true><<<GEMM_GRID, T>>>(nullptr, W3);
    agg_init_kernel <NCLS, true><<<(N_NODES * NCLS + T - 1) / T, T>>>(b3, out);
    agg_edges_kernel<NCLS, true><<<(N_EDGES * (NCLS / 4) + T - 1) / T, T>>>(out);
}

// round 4
// speedup vs baseline: 2.5233x; 2.5233x over previous
#include <cuda_runtime.h>

#define N_NODES 100000
#define N_EDGES 1600000
#define F_IN    128
#define HID     64
#define NCLS    16
#define NB_SCAN ((N_NODES + 1023) / 1024)

// ---------------- scratch (no allocations allowed) ----------------
__device__ int   g_is64;
__device__ float g_dinv[N_NODES];
__device__ int   g_src[N_EDGES];
__device__ int   g_dst[N_EDGES];
__device__ int   g_cnt[N_NODES];
__device__ int   g_px[N_NODES];
__device__ int   g_bsum[NB_SCAN];
__device__ int   g_bofs[NB_SCAN];
__device__ int   g_rowptr[N_NODES + 1];
__device__ int   g_fill[N_NODES];
__device__ int   g_esrc[N_EDGES];      // CSR: src sorted by dst
__device__ float g_enorm[N_EDGES];     // CSR: norm per sorted edge
__device__ __align__(16) float g_xw[(size_t)N_NODES * HID];
__device__ __align__(16) float g_h [(size_t)N_NODES * HID];

// ---------------- edge-index dtype detection ----------------
__global__ void detect_kernel(const void* ei_raw) {
    const long long* e64 = (const long long*)ei_raw;
    int ok = 1;
    for (int i = 0; i < 16; i++) {
        long long v = e64[i];
        if (v < 0 || v >= N_NODES) ok = 0;
    }
    g_is64 = ok;
}

__global__ void zero_cnt_kernel() {
    int i = blockIdx.x * blockDim.x + threadIdx.x;
    if (i < N_NODES) g_cnt[i] = 0;
}

// sanitize indices + histogram of dst in one pass
__global__ void prep_hist_kernel(const void* ei_raw) {
    int e = blockIdx.x * blockDim.x + threadIdx.x;
    if (e >= N_EDGES) return;
    int s, d;
    if (g_is64) {
        const long long* e64 = (const long long*)ei_raw;
        s = (int)e64[e];
        d = (int)e64[(size_t)N_EDGES + e];
    } else {
        const int* e32 = (const int*)ei_raw;
        s = e32[e];
        d = e32[N_EDGES + e];
    }
    if ((unsigned)s >= N_NODES) s = 0;   // never a wild address
    if ((unsigned)d >= N_NODES) d = 0;
    g_src[e] = s;
    g_dst[e] = d;
    atomicAdd(&g_cnt[d], 1);
}

// ---------------- 2-level exclusive scan of g_cnt -> g_rowptr ----------------
__global__ void scan1_kernel() {
    __shared__ int s[1024];
    int t = threadIdx.x, b = blockIdx.x;
    int idx = b * 1024 + t;
    int v = (idx < N_NODES) ? g_cnt[idx] : 0;
    s[t] = v; __syncthreads();
    for (int off = 1; off < 1024; off <<= 1) {
        int add = (t >= off) ? s[t - off] : 0;
        __syncthreads();
        s[t] += add;
        __syncthreads();
    }
    int incl = s[t];
    if (idx < N_NODES) g_px[idx] = incl - v;
    if (t == 1023) g_bsum[b] = incl;
}

__global__ void scan2_kernel() {
    int run = 0;
    for (int b = 0; b < NB_SCAN; b++) { g_bofs[b] = run; run += g_bsum[b]; }
}

// rowptr/fill init + dinv (deg = cnt + 1 self-loop)
__global__ void scan3_kernel() {
    int idx = blockIdx.x * blockDim.x + threadIdx.x;
    if (idx < N_NODES) {
        int base = g_px[idx] + g_bofs[idx >> 10];
        g_rowptr[idx] = base;
        g_fill[idx]   = base;
        g_dinv[idx]   = rsqrtf(1.0f + (float)g_cnt[idx]);
    }
    if (idx == 0) g_rowptr[N_NODES] = N_EDGES;
}

// scatter edges into CSR order, computing norm on the way
__global__ void scatter_kernel() {
    int e = blockIdx.x * blockDim.x + threadIdx.x;
    if (e >= N_EDGES) return;
    int s = g_src[e];
    int d = g_dst[e];
    int pos = atomicAdd(&g_fill[d], 1);
    g_esrc[pos]  = s;
    g_enorm[pos] = g_dinv[s] * g_dinv[d];
}

// ---------------- GEMM: g_xw[node,:] = act(src[node,:]) @ W ----------------
// 8 warps/block, 4 nodes per warp: amortize Ws loads over 4 accumulator sets.
template<int K, int C, bool RELU, bool FROM_H>
__global__ void __launch_bounds__(256) gemm_kernel(const float* __restrict__ X,
                                                   const float* __restrict__ W) {
    __shared__ float Ws[K * C];
    __shared__ float xs[8][4][K];
    for (int i = threadIdx.x; i < K * C; i += 256) Ws[i] = W[i];
    __syncthreads();

    const int warp = threadIdx.x >> 5;
    const int lane = threadIdx.x & 31;
    constexpr int CP = (C + 31) / 32;

    for (int base = (blockIdx.x * 8 + warp) * 4; base < N_NODES;
         base += gridDim.x * 32) {
        #pragma unroll
        for (int n = 0; n < 4; n++) {
            int node = base + n;
            if (node < N_NODES) {
                for (int k = lane; k < K; k += 32) {
                    float v = FROM_H ? g_h[(size_t)node * K + k]
                                     : X  [(size_t)node * K + k];
                    if (RELU) v = fmaxf(v, 0.0f);
                    xs[warp][n][k] = v;
                }
            }
        }
        __syncwarp();

        float acc[4][CP];
        #pragma unroll
        for (int n = 0; n < 4; n++)
            #pragma unroll
            for (int j = 0; j < CP; j++) acc[n][j] = 0.0f;

        #pragma unroll 4
        for (int k = 0; k < K; k++) {
            float w[CP];
            #pragma unroll
            for (int j = 0; j < CP; j++) {
                int col = lane + 32 * j;
                w[j] = (col < C) ? Ws[k * C + col] : 0.0f;
            }
            #pragma unroll
            for (int n = 0; n < 4; n++) {
                float xv = xs[warp][n][k];
                #pragma unroll
                for (int j = 0; j < CP; j++)
                    acc[n][j] = fmaf(xv, w[j], acc[n][j]);
            }
        }

        #pragma unroll
        for (int n = 0; n < 4; n++) {
            int node = base + n;
            if (node < N_NODES) {
                #pragma unroll
                for (int j = 0; j < CP; j++) {
                    int col = lane + 32 * j;
                    if (col < C) g_xw[(size_t)node * C + col] = acc[n][j];
                }
            }
        }
        __syncwarp();
    }
}

// ---------------- pull aggregation (atomic-free) ----------------
// g_h[node,c] = b[c] + g_xw[node,c]*dinv^2 + sum_e g_xw[src,c]*norm[e]
__global__ void __launch_bounds__(256) pull64_kernel(const float* __restrict__ b) {
    int warp = threadIdx.x >> 5, lane = threadIdx.x & 31;
    int node = blockIdx.x * 8 + warp;
    if (node >= N_NODES) return;

    float di = g_dinv[node];
    float di2 = di * di;
    const float* xr = g_xw + (size_t)node * HID;
    float a0 = fmaf(xr[lane],      di2, b[lane]);
    float a1 = fmaf(xr[lane + 32], di2, b[lane + 32]);

    int e = g_rowptr[node], end = g_rowptr[node + 1];
    for (; e + 1 < end; e += 2) {
        int   s0 = g_esrc[e],     s1 = g_esrc[e + 1];
        float w0 = g_enorm[e],    w1 = g_enorm[e + 1];
        const float* r0 = g_xw + (size_t)s0 * HID;
        const float* r1 = g_xw + (size_t)s1 * HID;
        a0 = fmaf(r0[lane],      w0, a0);
        a1 = fmaf(r0[lane + 32], w0, a1);
        a0 = fmaf(r1[lane],      w1, a0);
        a1 = fmaf(r1[lane + 32], w1, a1);
    }
    if (e < end) {
        int   s0 = g_esrc[e];
        float w0 = g_enorm[e];
        const float* r0 = g_xw + (size_t)s0 * HID;
        a0 = fmaf(r0[lane],      w0, a0);
        a1 = fmaf(r0[lane + 32], w0, a1);
    }
    g_h[(size_t)node * HID + lane]      = a0;
    g_h[(size_t)node * HID + lane + 32] = a1;
}

// final layer, C=16: half-warp per edge-parity, shuffle-reduce
__global__ void __launch_bounds__(256) pull16_kernel(const float* __restrict__ b,
                                                     float* __restrict__ out) {
    int warp = threadIdx.x >> 5, lane = threadIdx.x & 31;
    int node = blockIdx.x * 8 + warp;
    if (node >= N_NODES) return;

    int col = lane & 15, eh = lane >> 4;
    float di = g_dinv[node];
    float a = 0.0f;
    if (eh == 0) a = fmaf(g_xw[(size_t)node * NCLS + col], di * di, b[col]);

    int start = g_rowptr[node], end = g_rowptr[node + 1];
    for (int e = start + eh; e < end; e += 2)
        a = fmaf(g_xw[(size_t)g_esrc[e] * NCLS + col], g_enorm[e], a);

    a += __shfl_xor_sync(0xFFFFFFFFu, a, 16);
    if (eh == 0) out[(size_t)node * NCLS + col] = a;
}

// ---------------- launch ----------------
extern "C" void kernel_launch(void* const* d_in, const int* in_sizes, int n_in,
                              void* d_out, int out_size) {
    const float* x  = (const float*)d_in[0];
    const void*  ei = d_in[1];
    const float* W1 = (const float*)d_in[2];
    const float* b1 = (const float*)d_in[3];
    const float* W2 = (const float*)d_in[4];
    const float* b2 = (const float*)d_in[5];
    const float* W3 = (const float*)d_in[6];
    const float* b3 = (const float*)d_in[7];
    float* out = (float*)d_out;

    const int T = 256;
    const int nb_nodes = (N_NODES + T - 1) / T;
    const int nb_edges = (N_EDGES + T - 1) / T;
    const int nb_pull  = (N_NODES + 7) / 8;

    // CSR build + normalization
    detect_kernel   <<<1, 1>>>(ei);
    zero_cnt_kernel <<<nb_nodes, T>>>();
    prep_hist_kernel<<<nb_edges, T>>>(ei);
    scan1_kernel    <<<NB_SCAN, 1024>>>();
    scan2_kernel    <<<1, 1>>>();
    scan3_kernel    <<<nb_nodes, T>>>();
    scatter_kernel  <<<nb_edges, T>>>();

    const int GEMM_GRID = 592;

    // layer 1
    gemm_kernel<F_IN, HID, false, false><<<GEMM_GRID, T>>>(x, W1);
    pull64_kernel<<<nb_pull, T>>>(b1);
    // layer 2
    gemm_kernel<HID, HID, true, true><<<GEMM_GRID, T>>>(nullptr, W2);
    pull64_kernel<<<nb_pull, T>>>(b2);
    // layer 3
    gemm_kernel<HID, NCLS, true, true><<<GEMM_GRID, T>>>(nullptr, W3);
    pull16_kernel<<<nb_pull, T>>>(b3, out);
}

// round 6
// speedup vs baseline: 2.7651x; 1.0958x over previous
#include <cuda_runtime.h>

#define N_NODES 100000
#define N_EDGES 1600000
#define F_IN    128
#define HID     64
#define NCLS    16
#define NB_SCAN ((N_NODES + 1023) / 1024)

typedef unsigned long long ull;

// ---------------- f32x2 helpers ----------------
__device__ __forceinline__ ull pack2(float x, float y) {
    ull r; asm("mov.b64 %0, {%1, %2};" : "=l"(r) : "f"(x), "f"(y)); return r;
}
__device__ __forceinline__ void unpack2(ull v, float& x, float& y) {
    asm("mov.b64 {%0, %1}, %2;" : "=f"(x), "=f"(y) : "l"(v));
}
__device__ __forceinline__ ull fma2(ull a, ull b, ull c) {
    ull d; asm("fma.rn.f32x2 %0, %1, %2, %3;" : "=l"(d) : "l"(a), "l"(b), "l"(c)); return d;
}

// ---------------- scratch ----------------
__device__ int   g_is64;
__device__ float g_dinv[N_NODES];
__device__ __align__(8) int2 g_sd[N_EDGES];     // sanitized (src, dst)
__device__ int   g_cnt[N_NODES];
__device__ int   g_px[N_NODES];
__device__ int   g_bsum[NB_SCAN];
__device__ int   g_rowptr[N_NODES + 1];
__device__ int   g_fill[N_NODES];
__device__ __align__(8) int2 g_epk[N_EDGES];    // CSR: (src, norm-bits) sorted by dst
__device__ __align__(16) float g_xw[(size_t)N_NODES * HID];
__device__ __align__(16) float g_h [(size_t)N_NODES * HID];

static_assert(sizeof(int2) == 8, "int2 packing");
static_assert(sizeof(ull) == 8, "f32x2 packing");

// ---------------- prep: zero counts + dtype detect ----------------
__global__ void zero_detect_kernel(const void* ei_raw) {
    int i = blockIdx.x * blockDim.x + threadIdx.x;
    if (i < N_NODES) g_cnt[i] = 0;
    if (i == 0) {
        const long long* e64 = (const long long*)ei_raw;
        int ok = 1;
        for (int k = 0; k < 16; k++) {
            long long v = e64[k];
            if (v < 0 || v >= N_NODES) ok = 0;
        }
        g_is64 = ok;
    }
}

// sanitize indices + histogram of dst
__global__ void prep_hist_kernel(const void* ei_raw) {
    int e = blockIdx.x * blockDim.x + threadIdx.x;
    if (e >= N_EDGES) return;
    int s, d;
    if (g_is64) {
        const long long* e64 = (const long long*)ei_raw;
        s = (int)e64[e];
        d = (int)e64[(size_t)N_EDGES + e];
    } else {
        const int* e32 = (const int*)ei_raw;
        s = e32[e];
        d = e32[N_EDGES + e];
    }
    if ((unsigned)s >= N_NODES) s = 0;   // never a wild address
    if ((unsigned)d >= N_NODES) d = 0;
    g_sd[e] = make_int2(s, d);
    atomicAdd(&g_cnt[d], 1);
}

// ---------------- 2-level scan ----------------
__global__ void scan1_kernel() {
    __shared__ int s[1024];
    int t = threadIdx.x, b = blockIdx.x;
    int idx = b * 1024 + t;
    int v = (idx < N_NODES) ? g_cnt[idx] : 0;
    s[t] = v; __syncthreads();
    for (int off = 1; off < 1024; off <<= 1) {
        int add = (t >= off) ? s[t - off] : 0;
        __syncthreads();
        s[t] += add;
        __syncthreads();
    }
    int incl = s[t];
    if (idx < N_NODES) g_px[idx] = incl - v;
    if (t == 1023) g_bsum[b] = incl;
}

// rowptr/fill/dinv, with block-offset computed in-kernel (folds old scan2)
__global__ void scan3_kernel() {
    __shared__ int s_ofs;
    int t = threadIdx.x;
    int sb = (blockIdx.x * 256) >> 10;      // all 256 idx in this block share one scan1 block
    if (t < 32) {
        int acc = 0;
        for (int i = t; i < sb; i += 32) acc += g_bsum[i];
        #pragma unroll
        for (int off = 16; off > 0; off >>= 1)
            acc += __shfl_xor_sync(0xFFFFFFFFu, acc, off);
        if (t == 0) s_ofs = acc;
    }
    __syncthreads();
    int idx = blockIdx.x * 256 + t;
    if (idx < N_NODES) {
        int base = g_px[idx] + s_ofs;
        g_rowptr[idx] = base;
        g_fill[idx]   = base;
        g_dinv[idx]   = rsqrtf(1.0f + (float)g_cnt[idx]);
    }
    if (idx == 0) g_rowptr[N_NODES] = N_EDGES;
}

// scatter edges into CSR order with norm packed alongside src
__global__ void scatter_kernel() {
    int e = blockIdx.x * blockDim.x + threadIdx.x;
    if (e >= N_EDGES) return;
    int2 sd = g_sd[e];
    int pos = atomicAdd(&g_fill[sd.y], 1);
    float nrm = g_dinv[sd.x] * g_dinv[sd.y];
    g_epk[pos] = make_int2(sd.x, __float_as_int(nrm));
}

// ---------------- GEMM C=64 via f32x2: lane owns cols (2l, 2l+1) ----------------
template<int K, bool RELU, bool FROM_H>
__global__ void __launch_bounds__(256) gemm64_kernel(const float* __restrict__ X,
                                                     const float* __restrict__ W) {
    __shared__ ull    Ws2[K * 32];       // W[k][2c..2c+1] packed
    __shared__ float4 xs4[8][4][K / 4];
    const ull* Wv = (const ull*)W;       // bitwise copy of float pairs
    for (int i = threadIdx.x; i < K * 32; i += 256) Ws2[i] = Wv[i];
    __syncthreads();

    const int warp = threadIdx.x >> 5;
    const int lane = threadIdx.x & 31;

    for (int base = (blockIdx.x * 8 + warp) * 4; base < N_NODES;
         base += gridDim.x * 32) {
        #pragma unroll
        for (int n = 0; n < 4; n++) {
            int node = base + n;
            if (node < N_NODES) {
                float* xrow = (float*)&xs4[warp][n][0];
                for (int k = lane; k < K; k += 32) {
                    float v = FROM_H ? g_h[(size_t)node * K + k]
                                     : X  [(size_t)node * K + k];
                    if (RELU) v = fmaxf(v, 0.0f);
                    xrow[k] = v;
                }
            }
        }
        __syncwarp();

        ull acc[4] = {0ull, 0ull, 0ull, 0ull};   // bits 0 == {0.0f, 0.0f}

        #pragma unroll 4
        for (int k4 = 0; k4 < K / 4; k4++) {
            float4 xv[4];
            #pragma unroll
            for (int n = 0; n < 4; n++) xv[n] = xs4[warp][n][k4];
            #pragma unroll
            for (int kk = 0; kk < 4; kk++) {
                ull w = Ws2[(k4 * 4 + kk) * 32 + lane];
                float x0 = (kk == 0) ? xv[0].x : (kk == 1) ? xv[0].y : (kk == 2) ? xv[0].z : xv[0].w;
                float x1 = (kk == 0) ? xv[1].x : (kk == 1) ? xv[1].y : (kk == 2) ? xv[1].z : xv[1].w;
                float x2 = (kk == 0) ? xv[2].x : (kk == 1) ? xv[2].y : (kk == 2) ? xv[2].z : xv[2].w;
                float x3 = (kk == 0) ? xv[3].x : (kk == 1) ? xv[3].y : (kk == 2) ? xv[3].z : xv[3].w;
                acc[0] = fma2(w, pack2(x0, x0), acc[0]);
                acc[1] = fma2(w, pack2(x1, x1), acc[1]);
                acc[2] = fma2(w, pack2(x2, x2), acc[2]);
                acc[3] = fma2(w, pack2(x3, x3), acc[3]);
            }
        }

        #pragma unroll
        for (int n = 0; n < 4; n++) {
            int node = base + n;
            if (node < N_NODES) {
                float lo, hi; unpack2(acc[n], lo, hi);
                ((float2*)(g_xw + (size_t)node * HID))[lane] = make_float2(lo, hi);
            }
        }
        __syncwarp();
    }
}

// ---------------- GEMM C=16 (layer 3, small): scalar path ----------------
template<int K>
__global__ void __launch_bounds__(256) gemm16_kernel(const float* __restrict__ W) {
    __shared__ float Ws[K * NCLS];
    __shared__ float xs[8][4][K];
    for (int i = threadIdx.x; i < K * NCLS; i += 256) Ws[i] = W[i];
    __syncthreads();

    const int warp = threadIdx.x >> 5;
    const int lane = threadIdx.x & 31;
    const int col  = lane & 15;
    const int half = lane >> 4;          // half-warps split the K range

    for (int base = (blockIdx.x * 8 + warp) * 4; base < N_NODES;
         base += gridDim.x * 32) {
        #pragma unroll
        for (int n = 0; n < 4; n++) {
            int node = base + n;
            if (node < N_NODES)
                for (int k = lane; k < K; k += 32)
                    xs[warp][n][k] = fmaxf(g_h[(size_t)node * K + k], 0.0f);
        }
        __syncwarp();

        float acc[4] = {0, 0, 0, 0};
        #pragma unroll 4
        for (int k = half * (K / 2); k < (half + 1) * (K / 2); k++) {
            float w = Ws[k * NCLS + col];
            #pragma unroll
            for (int n = 0; n < 4; n++)
                acc[n] = fmaf(xs[warp][n][k], w, acc[n]);
        }
        #pragma unroll
        for (int n = 0; n < 4; n++) {
            acc[n] += __shfl_xor_sync(0xFFFFFFFFu, acc[n], 16);
            int node = base + n;
            if (node < N_NODES && half == 0)
                g_xw[(size_t)node * NCLS + col] = acc[n];
        }
        __syncwarp();
    }
}

// ---------------- pull aggregation (atomic-free, f32x2) ----------------
// g_h[node,c] = b[c] + g_xw[node,c]*dinv^2 + sum_e g_xw[src,c]*norm[e]
__global__ void __launch_bounds__(256) pull64_kernel(const float* __restrict__ b) {
    int warp = threadIdx.x >> 5, lane = threadIdx.x & 31;
    int node = blockIdx.x * 8 + warp;
    if (node >= N_NODES) return;

    float2 bb = ((const float2*)b)[lane];
    float di = g_dinv[node], di2 = di * di;
    float2 xr = ((const float2*)(g_xw + (size_t)node * HID))[lane];
    ull acc = pack2(fmaf(xr.x, di2, bb.x), fmaf(xr.y, di2, bb.y));

    int e = g_rowptr[node], end = g_rowptr[node + 1];
    for (; e + 3 < end; e += 4) {
        int2 p0 = g_epk[e],     p1 = g_epk[e + 1];
        int2 p2 = g_epk[e + 2], p3 = g_epk[e + 3];
        float2 v0 = ((const float2*)(g_xw + (size_t)p0.x * HID))[lane];
        float2 v1 = ((const float2*)(g_xw + (size_t)p1.x * HID))[lane];
        float2 v2 = ((const float2*)(g_xw + (size_t)p2.x * HID))[lane];
        float2 v3 = ((const float2*)(g_xw + (size_t)p3.x * HID))[lane];
        float w0 = __int_as_float(p0.y), w1 = __int_as_float(p1.y);
        float w2 = __int_as_float(p2.y), w3 = __int_as_float(p3.y);
        acc = fma2(pack2(v0.x, v0.y), pack2(w0, w0), acc);
        acc = fma2(pack2(v1.x, v1.y), pack2(w1, w1), acc);
        acc = fma2(pack2(v2.x, v2.y), pack2(w2, w2), acc);
        acc = fma2(pack2(v3.x, v3.y), pack2(w3, w3), acc);
    }
    for (; e < end; e++) {
        int2 p = g_epk[e];
        float2 v = ((const float2*)(g_xw + (size_t)p.x * HID))[lane];
        float w = __int_as_float(p.y);
        acc = fma2(pack2(v.x, v.y), pack2(w, w), acc);
    }
    float lo, hi; unpack2(acc, lo, hi);
    ((float2*)(g_h + (size_t)node * HID))[lane] = make_float2(lo, hi);
}

// final layer, C=16: half-warp per edge-parity, shuffle-reduce
__global__ void __launch_bounds__(256) pull16_kernel(const float* __restrict__ b,
                                                     float* __restrict__ out) {
    int warp = threadIdx.x >> 5, lane = threadIdx.x & 31;
    int node = blockIdx.x * 8 + warp;
    if (node >= N_NODES) return;

    int col = lane & 15, eh = lane >> 4;
    float di = g_dinv[node];
    float a = 0.0f;
    if (eh == 0) a = fmaf(g_xw[(size_t)node * NCLS + col], di * di, b[col]);

    int start = g_rowptr[node], end = g_rowptr[node + 1];
    for (int e = start + eh; e < end; e += 2) {
        int2 p = g_epk[e];
        a = fmaf(g_xw[(size_t)p.x * NCLS + col], __int_as_float(p.y), a);
    }
    a += __shfl_xor_sync(0xFFFFFFFFu, a, 16);
    if (eh == 0) out[(size_t)node * NCLS + col] = a;
}

// ---------------- launch ----------------
extern "C" void kernel_launch(void* const* d_in, const int* in_sizes, int n_in,
                              void* d_out, int out_size) {
    const float* x  = (const float*)d_in[0];
    const void*  ei = d_in[1];
    const float* W1 = (const float*)d_in[2];
    const float* b1 = (const float*)d_in[3];
    const float* W2 = (const float*)d_in[4];
    const float* b2 = (const float*)d_in[5];
    const float* W3 = (const float*)d_in[6];
    const float* b3 = (const float*)d_in[7];
    float* out = (float*)d_out;

    const int T = 256;
    const int nb_nodes = (N_NODES + T - 1) / T;
    const int nb_edges = (N_EDGES + T - 1) / T;
    const int nb_pull  = (N_NODES + 7) / 8;

    // CSR build + normalization (5 launches)
    zero_detect_kernel<<<nb_nodes, T>>>(ei);
    prep_hist_kernel  <<<nb_edges, T>>>(ei);
    scan1_kernel      <<<NB_SCAN, 1024>>>();
    scan3_kernel      <<<nb_nodes, T>>>();
    scatter_kernel    <<<nb_edges, T>>>();

    const int GEMM_GRID = 592;

    // layer 1
    gemm64_kernel<F_IN, false, false><<<GEMM_GRID, T>>>(x, W1);
    pull64_kernel<<<nb_pull, T>>>(b1);
    // layer 2
    gemm64_kernel<HID, true, true><<<GEMM_GRID, T>>>(nullptr, W2);
    pull64_kernel<<<nb_pull, T>>>(b2);
    // layer 3
    gemm16_kernel<HID><<<GEMM_GRID, T>>>(W3);
    pull16_kernel<<<nb_pull, T>>>(b3, out);
}

// round 8
// speedup vs baseline: 2.9043x; 1.0503x over previous
#include <cuda_runtime.h>

#define N_NODES 100000
#define N_EDGES 1600000
#define F_IN    128
#define HID     64
#define NCLS    16
#define NB_SCAN ((N_NODES + 1023) / 1024)

typedef unsigned long long ull;

// ---------------- f32x2 helpers ----------------
__device__ __forceinline__ ull pack2(float x, float y) {
    ull r; asm("mov.b64 %0, {%1, %2};" : "=l"(r) : "f"(x), "f"(y)); return r;
}
__device__ __forceinline__ void unpack2(ull v, float& x, float& y) {
    asm("mov.b64 {%0, %1}, %2;" : "=f"(x), "=f"(y) : "l"(v));
}
__device__ __forceinline__ ull fma2(ull a, ull b, ull c) {
    ull d; asm("fma.rn.f32x2 %0, %1, %2, %3;" : "=l"(d) : "l"(a), "l"(b), "l"(c)); return d;
}

// ---------------- scratch ----------------
__device__ int   g_is64;
__device__ float g_dinv[N_NODES];
__device__ __align__(8)  int2 g_sd[N_EDGES];    // sanitized (src, dst)
__device__ int   g_cnt[N_NODES];
__device__ int   g_px[N_NODES];
__device__ int   g_bsum[NB_SCAN];
__device__ int   g_rowptr[N_NODES + 1];
__device__ int   g_fill[N_NODES];
__device__ __align__(16) int2 g_epk[N_EDGES];   // CSR: (src, norm-bits) sorted by dst
__device__ __align__(16) float g_xw[(size_t)N_NODES * HID];
__device__ __align__(16) float g_h [(size_t)N_NODES * HID];

// ---------------- prep: zero counts + dtype detect ----------------
__global__ void zero_detect_kernel(const void* ei_raw) {
    int i = blockIdx.x * blockDim.x + threadIdx.x;
    if (i < N_NODES) g_cnt[i] = 0;
    if (i == 0) {
        const long long* e64 = (const long long*)ei_raw;
        int ok = 1;
        for (int k = 0; k < 16; k++) {
            long long v = e64[k];
            if (v < 0 || v >= N_NODES) ok = 0;
        }
        g_is64 = ok;
    }
}

// sanitize indices + histogram of dst
__global__ void prep_hist_kernel(const void* ei_raw) {
    int e = blockIdx.x * blockDim.x + threadIdx.x;
    if (e >= N_EDGES) return;
    int s, d;
    if (g_is64) {
        const long long* e64 = (const long long*)ei_raw;
        s = (int)e64[e];
        d = (int)e64[(size_t)N_EDGES + e];
    } else {
        const int* e32 = (const int*)ei_raw;
        s = e32[e];
        d = e32[N_EDGES + e];
    }
    if ((unsigned)s >= N_NODES) s = 0;   // never a wild address
    if ((unsigned)d >= N_NODES) d = 0;
    g_sd[e] = make_int2(s, d);
    atomicAdd(&g_cnt[d], 1);
}

// ---------------- 2-level scan ----------------
__global__ void scan1_kernel() {
    __shared__ int s[1024];
    int t = threadIdx.x, b = blockIdx.x;
    int idx = b * 1024 + t;
    int v = (idx < N_NODES) ? g_cnt[idx] : 0;
    s[t] = v; __syncthreads();
    for (int off = 1; off < 1024; off <<= 1) {
        int add = (t >= off) ? s[t - off] : 0;
        __syncthreads();
        s[t] += add;
        __syncthreads();
    }
    int incl = s[t];
    if (idx < N_NODES) g_px[idx] = incl - v;
    if (t == 1023) g_bsum[b] = incl;
}

// rowptr/fill/dinv, with block-offset computed in-kernel
__global__ void scan3_kernel() {
    __shared__ int s_ofs;
    int t = threadIdx.x;
    int sb = (blockIdx.x * 256) >> 10;
    if (t < 32) {
        int acc = 0;
        for (int i = t; i < sb; i += 32) acc += g_bsum[i];
        #pragma unroll
        for (int off = 16; off > 0; off >>= 1)
            acc += __shfl_xor_sync(0xFFFFFFFFu, acc, off);
        if (t == 0) s_ofs = acc;
    }
    __syncthreads();
    int idx = blockIdx.x * 256 + t;
    if (idx < N_NODES) {
        int base = g_px[idx] + s_ofs;
        g_rowptr[idx] = base;
        g_fill[idx]   = base;
        g_dinv[idx]   = rsqrtf(1.0f + (float)g_cnt[idx]);
    }
    if (idx == 0) g_rowptr[N_NODES] = N_EDGES;
}

// scatter edges into CSR order with norm packed alongside src
__global__ void scatter_kernel() {
    int e = blockIdx.x * blockDim.x + threadIdx.x;
    if (e >= N_EDGES) return;
    int2 sd = g_sd[e];
    int pos = atomicAdd(&g_fill[sd.y], 1);
    float nrm = g_dinv[sd.x] * g_dinv[sd.y];
    g_epk[pos] = make_int2(sd.x, __float_as_int(nrm));
}

// ---------------- GEMM C=64 via f32x2: lane owns cols (2l, 2l+1) ----------------
template<int K, bool RELU, bool FROM_H>
__global__ void __launch_bounds__(256) gemm64_kernel(const float* __restrict__ X,
                                                     const float* __restrict__ W) {
    __shared__ ull    Ws2[K * 32];       // W[k][2c..2c+1] packed
    __shared__ float4 xs4[8][4][K / 4];
    const ull* Wv = (const ull*)W;
    for (int i = threadIdx.x; i < K * 32; i += 256) Ws2[i] = Wv[i];
    __syncthreads();

    const int warp = threadIdx.x >> 5;
    const int lane = threadIdx.x & 31;

    for (int base = (blockIdx.x * 8 + warp) * 4; base < N_NODES;
         base += gridDim.x * 32) {
        #pragma unroll
        for (int n = 0; n < 4; n++) {
            int node = base + n;
            if (node < N_NODES) {
                float* xrow = (float*)&xs4[warp][n][0];
                for (int k = lane; k < K; k += 32) {
                    float v = FROM_H ? g_h[(size_t)node * K + k]
                                     : X  [(size_t)node * K + k];
                    if (RELU) v = fmaxf(v, 0.0f);
                    xrow[k] = v;
                }
            }
        }
        __syncwarp();

        ull acc[4] = {0ull, 0ull, 0ull, 0ull};

        #pragma unroll 4
        for (int k4 = 0; k4 < K / 4; k4++) {
            float4 xv[4];
            #pragma unroll
            for (int n = 0; n < 4; n++) xv[n] = xs4[warp][n][k4];
            #pragma unroll
            for (int kk = 0; kk < 4; kk++) {
                ull w = Ws2[(k4 * 4 + kk) * 32 + lane];
                float x0 = (kk == 0) ? xv[0].x : (kk == 1) ? xv[0].y : (kk == 2) ? xv[0].z : xv[0].w;
                float x1 = (kk == 0) ? xv[1].x : (kk == 1) ? xv[1].y : (kk == 2) ? xv[1].z : xv[1].w;
                float x2 = (kk == 0) ? xv[2].x : (kk == 1) ? xv[2].y : (kk == 2) ? xv[2].z : xv[2].w;
                float x3 = (kk == 0) ? xv[3].x : (kk == 1) ? xv[3].y : (kk == 2) ? xv[3].z : xv[3].w;
                acc[0] = fma2(w, pack2(x0, x0), acc[0]);
                acc[1] = fma2(w, pack2(x1, x1), acc[1]);
                acc[2] = fma2(w, pack2(x2, x2), acc[2]);
                acc[3] = fma2(w, pack2(x3, x3), acc[3]);
            }
        }

        #pragma unroll
        for (int n = 0; n < 4; n++) {
            int node = base + n;
            if (node < N_NODES) {
                float lo, hi; unpack2(acc[n], lo, hi);
                ((float2*)(g_xw + (size_t)node * HID))[lane] = make_float2(lo, hi);
            }
        }
        __syncwarp();
    }
}

// ---------------- GEMM C=16 (layer 3) ----------------
template<int K>
__global__ void __launch_bounds__(256) gemm16_kernel(const float* __restrict__ W) {
    __shared__ float Ws[K * NCLS];
    __shared__ float xs[8][4][K];
    for (int i = threadIdx.x; i < K * NCLS; i += 256) Ws[i] = W[i];
    __syncthreads();

    const int warp = threadIdx.x >> 5;
    const int lane = threadIdx.x & 31;
    const int col  = lane & 15;
    const int half = lane >> 4;

    for (int base = (blockIdx.x * 8 + warp) * 4; base < N_NODES;
         base += gridDim.x * 32) {
        #pragma unroll
        for (int n = 0; n < 4; n++) {
            int node = base + n;
            if (node < N_NODES)
                for (int k = lane; k < K; k += 32)
                    xs[warp][n][k] = fmaxf(g_h[(size_t)node * K + k], 0.0f);
        }
        __syncwarp();

        float acc[4] = {0, 0, 0, 0};
        #pragma unroll 4
        for (int k = half * (K / 2); k < (half + 1) * (K / 2); k++) {
            float w = Ws[k * NCLS + col];
            #pragma unroll
            for (int n = 0; n < 4; n++)
                acc[n] = fmaf(xs[warp][n][k], w, acc[n]);
        }
        #pragma unroll
        for (int n = 0; n < 4; n++) {
            acc[n] += __shfl_xor_sync(0xFFFFFFFFu, acc[n], 16);
            int node = base + n;
            if (node < N_NODES && half == 0)
                g_xw[(size_t)node * NCLS + col] = acc[n];
        }
        __syncwarp();
    }
}

// ---------------- pull aggregation (atomic-free, f32x2, 8-edge unroll) ----------------
__device__ __forceinline__ ull edge_fma2(ull acc, int src, int wbits, int lane) {
    float2 v = ((const float2*)(g_xw + (size_t)src * HID))[lane];
    float w = __int_as_float(wbits);
    return fma2(pack2(v.x, v.y), pack2(w, w), acc);
}

__global__ void __launch_bounds__(256) pull64_kernel(const float* __restrict__ b) {
    int warp = threadIdx.x >> 5, lane = threadIdx.x & 31;
    int node = blockIdx.x * 8 + warp;
    if (node >= N_NODES) return;

    float2 bb = ((const float2*)b)[lane];
    float di = g_dinv[node], di2 = di * di;
    float2 xr = ((const float2*)(g_xw + (size_t)node * HID))[lane];
    ull acc = pack2(fmaf(xr.x, di2, bb.x), fmaf(xr.y, di2, bb.y));

    int e = g_rowptr[node], end = g_rowptr[node + 1];
    // peel to 16B alignment of g_epk (e even)
    if ((e & 1) && e < end) {
        int2 p = g_epk[e];
        acc = edge_fma2(acc, p.x, p.y, lane);
        e++;
    }
    for (; e + 7 < end; e += 8) {
        int4 q0 = *(const int4*)&g_epk[e];
        int4 q1 = *(const int4*)&g_epk[e + 2];
        int4 q2 = *(const int4*)&g_epk[e + 4];
        int4 q3 = *(const int4*)&g_epk[e + 6];
        acc = edge_fma2(acc, q0.x, q0.y, lane);
        acc = edge_fma2(acc, q0.z, q0.w, lane);
        acc = edge_fma2(acc, q1.x, q1.y, lane);
        acc = edge_fma2(acc, q1.z, q1.w, lane);
        acc = edge_fma2(acc, q2.x, q2.y, lane);
        acc = edge_fma2(acc, q2.z, q2.w, lane);
        acc = edge_fma2(acc, q3.x, q3.y, lane);
        acc = edge_fma2(acc, q3.z, q3.w, lane);
    }
    for (; e < end; e++) {
        int2 p = g_epk[e];
        acc = edge_fma2(acc, p.x, p.y, lane);
    }
    float lo, hi; unpack2(acc, lo, hi);
    ((float2*)(g_h + (size_t)node * HID))[lane] = make_float2(lo, hi);
}

// final layer, C=16: half-warp per edge-parity, shuffle-reduce
__global__ void __launch_bounds__(256) pull16_kernel(const float* __restrict__ b,
                                                     float* __restrict__ out) {
    int warp = threadIdx.x >> 5, lane = threadIdx.x & 31;
    int node = blockIdx.x * 8 + warp;
    if (node >= N_NODES) return;

    int col = lane & 15, eh = lane >> 4;
    float di = g_dinv[node];
    float a = 0.0f;
    if (eh == 0) a = fmaf(g_xw[(size_t)node * NCLS + col], di * di, b[col]);

    int start = g_rowptr[node], end = g_rowptr[node + 1];
    for (int e = start + eh; e < end; e += 2) {
        int2 p = g_epk[e];
        a = fmaf(g_xw[(size_t)p.x * NCLS + col], __int_as_float(p.y), a);
    }
    a += __shfl_xor_sync(0xFFFFFFFFu, a, 16);
    if (eh == 0) out[(size_t)node * NCLS + col] = a;
}

// ---------------- launch ----------------
extern "C" void kernel_launch(void* const* d_in, const int* in_sizes, int n_in,
                              void* d_out, int out_size) {
    const float* x  = (const float*)d_in[0];
    const void*  ei = d_in[1];
    const float* W1 = (const float*)d_in[2];
    const float* b1 = (const float*)d_in[3];
    const float* W2 = (const float*)d_in[4];
    const float* b2 = (const float*)d_in[5];
    const float* W3 = (const float*)d_in[6];
    const float* b3 = (const float*)d_in[7];
    float* out = (float*)d_out;

    // One-time side stream + events, FAIL-SAFE: if any creation errors (e.g.
    // blocked by the harness's enforcement), fall back to fully serial
    // single-stream ordering. Mode is fixed after the first (pre-capture)
    // call, so captured work is deterministic.
    static int          s_mode = -1;          // -1 unset, 1 fork-join, 0 serial
    static cudaStream_t s_side;
    static cudaEvent_t  ev_fork, ev_join;
    if (s_mode < 0) {
        bool ok = (cudaStreamCreateWithFlags(&s_side, cudaStreamNonBlocking) == cudaSuccess)
               && (cudaEventCreateWithFlags(&ev_fork, cudaEventDisableTiming) == cudaSuccess)
               && (cudaEventCreateWithFlags(&ev_join, cudaEventDisableTiming) == cudaSuccess);
        cudaGetLastError();                   // clear any sticky error from a failed create
        s_mode = ok ? 1 : 0;
    }

    const int T = 256;
    const int nb_nodes = (N_NODES + T - 1) / T;
    const int nb_edges = (N_EDGES + T - 1) / T;
    const int nb_pull  = (N_NODES + 7) / 8;
    const int GEMM_GRID = 592;

    if (s_mode == 1) {
        // fork: layer-1 GEMM (independent of edge prep) on side stream
        cudaEventRecord(ev_fork, 0);
        cudaStreamWaitEvent(s_side, ev_fork, 0);
        gemm64_kernel<F_IN, false, false><<<GEMM_GRID, T, 0, s_side>>>(x, W1);
        cudaEventRecord(ev_join, s_side);
    }

    // CSR build + normalization on main stream (concurrent with gemm1 if forked)
    zero_detect_kernel<<<nb_nodes, T>>>(ei);
    prep_hist_kernel  <<<nb_edges, T>>>(ei);
    scan1_kernel      <<<NB_SCAN, 1024>>>();
    scan3_kernel      <<<nb_nodes, T>>>();
    scatter_kernel    <<<nb_edges, T>>>();

    if (s_mode == 1) {
        cudaStreamWaitEvent(0, ev_join, 0);   // join before pull1
    } else {
        gemm64_kernel<F_IN, false, false><<<GEMM_GRID, T>>>(x, W1);  // serial fallback
    }

    pull64_kernel<<<nb_pull, T>>>(b1);
    // layer 2
    gemm64_kernel<HID, true, true><<<GEMM_GRID, T>>>(nullptr, W2);
    pull64_kernel<<<nb_pull, T>>>(b2);
    // layer 3
    gemm16_kernel<HID><<<GEMM_GRID, T>>>(W3);
    pull16_kernel<<<nb_pull, T>>>(b3, out);
}

// round 11
// speedup vs baseline: 2.9117x; 1.0025x over previous
#include <cuda_runtime.h>
#include <cuda_fp16.h>

#define N_NODES 100000
#define N_EDGES 1600000
#define F_IN    128
#define HID     64
#define NCLS    16
#define NB_SCAN ((N_NODES + 1023) / 1024)

typedef unsigned long long ull;

// ---------------- f32x2 helpers ----------------
__device__ __forceinline__ ull pack2(float x, float y) {
    ull r; asm("mov.b64 %0, {%1, %2};" : "=l"(r) : "f"(x), "f"(y)); return r;
}
__device__ __forceinline__ void unpack2(ull v, float& x, float& y) {
    asm("mov.b64 {%0, %1}, %2;" : "=f"(x), "=f"(y) : "l"(v));
}
__device__ __forceinline__ ull fma2(ull a, ull b, ull c) {
    ull d; asm("fma.rn.f32x2 %0, %1, %2, %3;" : "=l"(d) : "l"(a), "l"(b), "l"(c)); return d;
}

// ---------------- scratch ----------------
__device__ float g_dinv[N_NODES];
__device__ __align__(8)  int2 g_sd[N_EDGES];    // sanitized (src, dst)
__device__ int   g_cnt[N_NODES];                // ALWAYS zero between launches
__device__ int   g_px[N_NODES];
__device__ int   g_bsum[NB_SCAN];
__device__ int   g_rowptr[N_NODES + 1];
__device__ int   g_fill[N_NODES];
__device__ __align__(16) int2 g_epk[N_EDGES];   // CSR: (src, norm-bits) sorted by dst
__device__ __align__(16) __half2 g_xwh[(size_t)N_NODES * (HID / 2)];  // fp16 GEMM out (layers 1,2)
__device__ __align__(16) float   g_xw [(size_t)N_NODES * NCLS];       // fp32 GEMM out (layer 3)
__device__ __align__(16) float   g_h  [(size_t)N_NODES * HID];        // aggregated hidden

// ---------------- prep: sanitize + histogram (dtype detect per block) ----------------
__global__ void prep_hist_kernel(const void* ei_raw) {
    __shared__ int s_is64;
    if (threadIdx.x == 0) {
        const long long* e64 = (const long long*)ei_raw;
        int ok = 1;
        #pragma unroll
        for (int k = 0; k < 16; k++) {
            long long v = e64[k];
            if (v < 0 || v >= N_NODES) ok = 0;
        }
        s_is64 = ok;
    }
    __syncthreads();
    int e = blockIdx.x * blockDim.x + threadIdx.x;
    if (e >= N_EDGES) return;
    int s, d;
    if (s_is64) {
        const long long* e64 = (const long long*)ei_raw;
        s = (int)e64[e];
        d = (int)e64[(size_t)N_EDGES + e];
    } else {
        const int* e32 = (const int*)ei_raw;
        s = e32[e];
        d = e32[N_EDGES + e];
    }
    if ((unsigned)s >= N_NODES) s = 0;   // never a wild address
    if ((unsigned)d >= N_NODES) d = 0;
    g_sd[e] = make_int2(s, d);
    atomicAdd(&g_cnt[d], 1);
}

// ---------------- 2-level scan ----------------
__global__ void scan1_kernel() {
    __shared__ int s[1024];
    int t = threadIdx.x, b = blockIdx.x;
    int idx = b * 1024 + t;
    int v = (idx < N_NODES) ? g_cnt[idx] : 0;
    s[t] = v; __syncthreads();
    for (int off = 1; off < 1024; off <<= 1) {
        int add = (t >= off) ? s[t - off] : 0;
        __syncthreads();
        s[t] += add;
        __syncthreads();
    }
    int incl = s[t];
    if (idx < N_NODES) g_px[idx] = incl - v;
    if (t == 1023) g_bsum[b] = incl;
}

// rowptr/fill/dinv, block-offset in-kernel; also re-zeroes g_cnt for next launch
__global__ void scan3_kernel() {
    __shared__ int s_ofs;
    int t = threadIdx.x;
    int sb = (blockIdx.x * 256) >> 10;
    if (t < 32) {
        int acc = 0;
        for (int i = t; i < sb; i += 32) acc += g_bsum[i];
        #pragma unroll
        for (int off = 16; off > 0; off >>= 1)
            acc += __shfl_xor_sync(0xFFFFFFFFu, acc, off);
        if (t == 0) s_ofs = acc;
    }
    __syncthreads();
    int idx = blockIdx.x * 256 + t;
    if (idx < N_NODES) {
        int base = g_px[idx] + s_ofs;
        g_rowptr[idx] = base;
        g_fill[idx]   = base;
        g_dinv[idx]   = rsqrtf(1.0f + (float)g_cnt[idx]);
        g_cnt[idx]    = 0;                  // self-clean: invariant "g_cnt == 0" restored
    }
    if (idx == 0) g_rowptr[N_NODES] = N_EDGES;
}

// scatter edges into CSR order with norm packed alongside src
__global__ void scatter_kernel() {
    int e = blockIdx.x * blockDim.x + threadIdx.x;
    if (e >= N_EDGES) return;
    int2 sd = g_sd[e];
    int pos = atomicAdd(&g_fill[sd.y], 1);
    float nrm = g_dinv[sd.x] * g_dinv[sd.y];
    g_epk[pos] = make_int2(sd.x, __float_as_int(nrm));
}

// ---------------- GEMM C=64 via f32x2, epilogue stores __half2 ----------------
template<int K, bool RELU, bool FROM_H>
__global__ void __launch_bounds__(256) gemm64_kernel(const float* __restrict__ X,
                                                     const float* __restrict__ W) {
    __shared__ ull    Ws2[K * 32];       // W[k][2c..2c+1] packed
    __shared__ float4 xs4[8][4][K / 4];
    const ull* Wv = (const ull*)W;
    for (int i = threadIdx.x; i < K * 32; i += 256) Ws2[i] = Wv[i];
    __syncthreads();

    const int warp = threadIdx.x >> 5;
    const int lane = threadIdx.x & 31;

    for (int base = (blockIdx.x * 8 + warp) * 4; base < N_NODES;
         base += gridDim.x * 32) {
        #pragma unroll
        for (int n = 0; n < 4; n++) {
            int node = base + n;
            if (node < N_NODES) {
                float* xrow = (float*)&xs4[warp][n][0];
                for (int k = lane; k < K; k += 32) {
                    float v = FROM_H ? g_h[(size_t)node * K + k]
                                     : X  [(size_t)node * K + k];
                    if (RELU) v = fmaxf(v, 0.0f);
                    xrow[k] = v;
                }
            }
        }
        __syncwarp();

        ull acc[4] = {0ull, 0ull, 0ull, 0ull};

        #pragma unroll 4
        for (int k4 = 0; k4 < K / 4; k4++) {
            float4 xv[4];
            #pragma unroll
            for (int n = 0; n < 4; n++) xv[n] = xs4[warp][n][k4];
            #pragma unroll
            for (int kk = 0; kk < 4; kk++) {
                ull w = Ws2[(k4 * 4 + kk) * 32 + lane];
                float x0 = (kk == 0) ? xv[0].x : (kk == 1) ? xv[0].y : (kk == 2) ? xv[0].z : xv[0].w;
                float x1 = (kk == 0) ? xv[1].x : (kk == 1) ? xv[1].y : (kk == 2) ? xv[1].z : xv[1].w;
                float x2 = (kk == 0) ? xv[2].x : (kk == 1) ? xv[2].y : (kk == 2) ? xv[2].z : xv[2].w;
                float x3 = (kk == 0) ? xv[3].x : (kk == 1) ? xv[3].y : (kk == 2) ? xv[3].z : xv[3].w;
                acc[0] = fma2(w, pack2(x0, x0), acc[0]);
                acc[1] = fma2(w, pack2(x1, x1), acc[1]);
                acc[2] = fma2(w, pack2(x2, x2), acc[2]);
                acc[3] = fma2(w, pack2(x3, x3), acc[3]);
            }
        }

        #pragma unroll
        for (int n = 0; n < 4; n++) {
            int node = base + n;
            if (node < N_NODES) {
                float lo, hi; unpack2(acc[n], lo, hi);
                g_xwh[(size_t)node * (HID / 2) + lane] = __floats2half2_rn(lo, hi);
            }
        }
        __syncwarp();
    }
}

// ---------------- GEMM C=16 (layer 3, fp32 out) ----------------
template<int K>
__global__ void __launch_bounds__(256) gemm16_kernel(const float* __restrict__ W) {
    __shared__ float Ws[K * NCLS];
    __shared__ float xs[8][4][K];
    for (int i = threadIdx.x; i < K * NCLS; i += 256) Ws[i] = W[i];
    __syncthreads();

    const int warp = threadIdx.x >> 5;
    const int lane = threadIdx.x & 31;
    const int col  = lane & 15;
    const int half = lane >> 4;

    for (int base = (blockIdx.x * 8 + warp) * 4; base < N_NODES;
         base += gridDim.x * 32) {
        #pragma unroll
        for (int n = 0; n < 4; n++) {
            int node = base + n;
            if (node < N_NODES)
                for (int k = lane; k < K; k += 32)
                    xs[warp][n][k] = fmaxf(g_h[(size_t)node * K + k], 0.0f);
        }
        __syncwarp();

        float acc[4] = {0, 0, 0, 0};
        #pragma unroll 4
        for (int k = half * (K / 2); k < (half + 1) * (K / 2); k++) {
            float w = Ws[k * NCLS + col];
            #pragma unroll
            for (int n = 0; n < 4; n++)
                acc[n] = fmaf(xs[warp][n][k], w, acc[n]);
        }
        #pragma unroll
        for (int n = 0; n < 4; n++) {
            acc[n] += __shfl_xor_sync(0xFFFFFFFFu, acc[n], 16);
            int node = base + n;
            if (node < N_NODES && half == 0)
                g_xw[(size_t)node * NCLS + col] = acc[n];
        }
        __syncwarp();
    }
}

// ---------------- pull aggregation (atomic-free, fp16 gathers, f32x2 accum) ----------------
__device__ __forceinline__ ull edge_fma2h(ull acc, int src, int wbits, int lane) {
    float2 v = __half22float2(g_xwh[(size_t)src * (HID / 2) + lane]);
    float w = __int_as_float(wbits);
    return fma2(pack2(v.x, v.y), pack2(w, w), acc);
}

__global__ void __launch_bounds__(256) pull64_kernel(const float* __restrict__ b) {
    int warp = threadIdx.x >> 5, lane = threadIdx.x & 31;
    int node = blockIdx.x * 8 + warp;
    if (node >= N_NODES) return;

    float2 bb = ((const float2*)b)[lane];
    float di = g_dinv[node], di2 = di * di;
    float2 xr = __half22float2(g_xwh[(size_t)node * (HID / 2) + lane]);
    ull acc = pack2(fmaf(xr.x, di2, bb.x), fmaf(xr.y, di2, bb.y));

    int e = g_rowptr[node], end = g_rowptr[node + 1];
    // peel to 16B alignment of g_epk (e even)
    if ((e & 1) && e < end) {
        int2 p = g_epk[e];
        acc = edge_fma2h(acc, p.x, p.y, lane);
        e++;
    }
    for (; e + 7 < end; e += 8) {
        int4 q0 = *(const int4*)&g_epk[e];
        int4 q1 = *(const int4*)&g_epk[e + 2];
        int4 q2 = *(const int4*)&g_epk[e + 4];
        int4 q3 = *(const int4*)&g_epk[e + 6];
        acc = edge_fma2h(acc, q0.x, q0.y, lane);
        acc = edge_fma2h(acc, q0.z, q0.w, lane);
        acc = edge_fma2h(acc, q1.x, q1.y, lane);
        acc = edge_fma2h(acc, q1.z, q1.w, lane);
        acc = edge_fma2h(acc, q2.x, q2.y, lane);
        acc = edge_fma2h(acc, q2.z, q2.w, lane);
        acc = edge_fma2h(acc, q3.x, q3.y, lane);
        acc = edge_fma2h(acc, q3.z, q3.w, lane);
    }
    for (; e < end; e++) {
        int2 p = g_epk[e];
        acc = edge_fma2h(acc, p.x, p.y, lane);
    }
    float lo, hi; unpack2(acc, lo, hi);
    ((float2*)(g_h + (size_t)node * HID))[lane] = make_float2(lo, hi);
}

// final layer, C=16 fp32: half-warp per edge-parity, shuffle-reduce
__global__ void __launch_bounds__(256) pull16_kernel(const float* __restrict__ b,
                                                     float* __restrict__ out) {
    int warp = threadIdx.x >> 5, lane = threadIdx.x & 31;
    int node = blockIdx.x * 8 + warp;
    if (node >= N_NODES) return;

    int col = lane & 15, eh = lane >> 4;
    float di = g_dinv[node];
    float a = 0.0f;
    if (eh == 0) a = fmaf(g_xw[(size_t)node * NCLS + col], di * di, b[col]);

    int start = g_rowptr[node], end = g_rowptr[node + 1];
    for (int e = start + eh; e < end; e += 2) {
        int2 p = g_epk[e];
        a = fmaf(g_xw[(size_t)p.x * NCLS + col], __int_as_float(p.y), a);
    }
    a += __shfl_xor_sync(0xFFFFFFFFu, a, 16);
    if (eh == 0) out[(size_t)node * NCLS + col] = a;
}

// ---------------- launch ----------------
extern "C" void kernel_launch(void* const* d_in, const int* in_sizes, int n_in,
                              void* d_out, int out_size) {
    const float* x  = (const float*)d_in[0];
    const void*  ei = d_in[1];
    const float* W1 = (const float*)d_in[2];
    const float* b1 = (const float*)d_in[3];
    const float* W2 = (const float*)d_in[4];
    const float* b2 = (const float*)d_in[5];
    const float* W3 = (const float*)d_in[6];
    const float* b3 = (const float*)d_in[7];
    float* out = (float*)d_out;

    // One-time side stream + events (fail-safe: serial fallback if creation fails).
    static int          s_mode = -1;
    static cudaStream_t s_side;
    static cudaEvent_t  ev_fork, ev_join;
    if (s_mode < 0) {
        bool ok = (cudaStreamCreateWithFlags(&s_side, cudaStreamNonBlocking) == cudaSuccess)
               && (cudaEventCreateWithFlags(&ev_fork, cudaEventDisableTiming) == cudaSuccess)
               && (cudaEventCreateWithFlags(&ev_join, cudaEventDisableTiming) == cudaSuccess);
        cudaGetLastError();
        s_mode = ok ? 1 : 0;
    }

    const int T = 256;
    const int nb_nodes = (N_NODES + T - 1) / T;
    const int nb_edges = (N_EDGES + T - 1) / T;
    const int nb_pull  = (N_NODES + 7) / 8;
    const int GEMM_GRID = 592;

    if (s_mode == 1) {
        // fork: layer-1 GEMM (independent of edge prep) on side stream
        cudaEventRecord(ev_fork, 0);
        cudaStreamWaitEvent(s_side, ev_fork, 0);
        gemm64_kernel<F_IN, false, false><<<GEMM_GRID, T, 0, s_side>>>(x, W1);
        cudaEventRecord(ev_join, s_side);
    }

    // CSR build + normalization (4 launches; g_cnt pre-zeroed by invariant)
    prep_hist_kernel<<<nb_edges, T>>>(ei);
    scan1_kernel    <<<NB_SCAN, 1024>>>();
    scan3_kernel    <<<nb_nodes, T>>>();
    scatter_kernel  <<<nb_edges, T>>>();

    if (s_mode == 1) {
        cudaStreamWaitEvent(0, ev_join, 0);   // join before pull1
    } else {
        gemm64_kernel<F_IN, false, false><<<GEMM_GRID, T>>>(x, W1);  // serial fallback
    }

    pull64_kernel<<<nb_pull, T>>>(b1);
    // layer 2
    gemm64_kernel<HID, true, true><<<GEMM_GRID, T>>>(nullptr, W2);
    pull64_kernel<<<nb_pull, T>>>(b2);
    // layer 3
    gemm16_kernel<HID><<<GEMM_GRID, T>>>(W3);
    pull16_kernel<<<nb_pull, T>>>(b3, out);
}